// round 1
// baseline (speedup 1.0000x reference)
#include <cuda_runtime.h>
#include <cuda_bf16.h>
#include <math.h>

#define Bb 2
#define Tt 2048
#define Dd 1024
#define Hh 16
#define Kknn 3
#define Mm 16384
#define HDd 64
#define Nn (Bb*Tt)          // 4096 rows
#define SCALE_F 4096.0f     // D * sqrt(H)

// ---------------- scratch (device globals; no allocation allowed) ----------------
__device__ float g_q[Nn*Dd];
__device__ float g_k[Nn*Dd];
__device__ float g_v[Nn*Dd];
__device__ float g_o[Nn*Dd];

// ---------------- GEMM: C[n,m] = sum_k A[n,k]*W[m,k] + bias[m] -------------------
// A: 4096 x 1024 row-major, W: 1024 x 1024 row-major (reduce over contiguous dim)
// Tile 128x128, BK=8, 256 threads, 8x8 per thread, interleaved mapping.
__global__ __launch_bounds__(256) void gemm3_kernel(
    const float* __restrict__ A,
    const float* __restrict__ W0, const float* __restrict__ b0, float* __restrict__ C0,
    const float* __restrict__ W1, const float* __restrict__ b1, float* __restrict__ C1,
    const float* __restrict__ W2, const float* __restrict__ b2, float* __restrict__ C2)
{
    const float* W; const float* bias; float* C;
    if (blockIdx.z == 0)      { W = W0; bias = b0; C = C0; }
    else if (blockIdx.z == 1) { W = W1; bias = b1; C = C1; }
    else                      { W = W2; bias = b2; C = C2; }

    __shared__ float As[8][128];
    __shared__ float Bs[8][128];

    const int tid  = threadIdx.x;
    const int row0 = blockIdx.y * 128;
    const int col0 = blockIdx.x * 128;
    const int lr = tid >> 1;          // 0..127
    const int lc = (tid & 1) << 2;    // 0 or 4
    const int ty = tid >> 4;          // 0..15
    const int tx = tid & 15;          // 0..15

    float acc[8][8];
#pragma unroll
    for (int i = 0; i < 8; i++)
#pragma unroll
        for (int j = 0; j < 8; j++) acc[i][j] = 0.f;

    const float* Aptr = A + (size_t)(row0 + lr) * Dd + lc;
    const float* Wptr = W + (size_t)(col0 + lr) * Dd + lc;

    for (int k0 = 0; k0 < Dd; k0 += 8) {
        float4 a4 = *(const float4*)(Aptr + k0);
        float4 b4 = *(const float4*)(Wptr + k0);
        As[lc + 0][lr] = a4.x; As[lc + 1][lr] = a4.y;
        As[lc + 2][lr] = a4.z; As[lc + 3][lr] = a4.w;
        Bs[lc + 0][lr] = b4.x; Bs[lc + 1][lr] = b4.y;
        Bs[lc + 2][lr] = b4.z; Bs[lc + 3][lr] = b4.w;
        __syncthreads();
#pragma unroll
        for (int kk = 0; kk < 8; kk++) {
            float ra[8], rb[8];
#pragma unroll
            for (int i = 0; i < 8; i++) ra[i] = As[kk][ty + i * 16];
#pragma unroll
            for (int j = 0; j < 8; j++) rb[j] = Bs[kk][tx + j * 16];
#pragma unroll
            for (int i = 0; i < 8; i++)
#pragma unroll
                for (int j = 0; j < 8; j++)
                    acc[i][j] = fmaf(ra[i], rb[j], acc[i][j]);
        }
        __syncthreads();
    }

#pragma unroll
    for (int i = 0; i < 8; i++) {
        int r = row0 + ty + i * 16;
#pragma unroll
        for (int j = 0; j < 8; j++) {
            int c = col0 + tx + j * 16;
            C[(size_t)r * Dd + c] = acc[i][j] + bias[c];
        }
    }
}

// ---------------- row L2-normalize over D (q and k, in place) --------------------
__global__ __launch_bounds__(256) void normalize_kernel()
{
    const int row = blockIdx.x;
    float* buf = (blockIdx.y == 0) ? g_q : g_k;
    float* p = buf + (size_t)row * Dd;
    const int tid = threadIdx.x;

    float4 v = *(float4*)(p + tid * 4);
    float ss = v.x * v.x + v.y * v.y + v.z * v.z + v.w * v.w;
#pragma unroll
    for (int o = 16; o; o >>= 1) ss += __shfl_xor_sync(0xffffffffu, ss, o);

    __shared__ float ws[8];
    if ((tid & 31) == 0) ws[tid >> 5] = ss;
    __syncthreads();
    __shared__ float s_inv;
    if (tid == 0) {
        float s = 0.f;
#pragma unroll
        for (int i = 0; i < 8; i++) s += ws[i];
        s_inv = 1.0f / fmaxf(sqrtf(s), 1e-12f);
    }
    __syncthreads();
    float inv = s_inv;
    v.x *= inv; v.y *= inv; v.z *= inv; v.w *= inv;
    *(float4*)(p + tid * 4) = v;
}

// ---------------- causal flash attention (fp32), 64x64 tiles --------------------
// grid: (T/64, H, B), 256 threads. Dynamic smem: Qs,Ks,Vs,Ss each 64x65 floats.
__global__ __launch_bounds__(256) void attn_kernel()
{
    extern __shared__ float smem[];
    float* Qs = smem;                 // 64*65
    float* Ks = Qs + 64 * 65;
    float* Vs = Ks + 64 * 65;
    float* Ss = Vs + 64 * 65;
    __shared__ float sm_m[64], sm_l[64], sm_scale[64];

    const int q0 = blockIdx.x * 64;
    const int h  = blockIdx.y;
    const int b  = blockIdx.z;
    const int tid = threadIdx.x;
    const int ty = tid >> 4;   // 0..15
    const int tx = tid & 15;   // 0..15

    const float* qbase = g_q + (size_t)(b * Tt) * Dd + h * HDd;
    const float* kbase = g_k + (size_t)(b * Tt) * Dd + h * HDd;
    const float* vbase = g_v + (size_t)(b * Tt) * Dd + h * HDd;

    // load Q tile (64 rows x 64 cols)
#pragma unroll
    for (int i = 0; i < 4; i++) {
        int r = ty + i * 16;
        int c = tx * 4;
        float4 v4 = *(const float4*)(qbase + (size_t)(q0 + r) * Dd + c);
        Qs[r * 65 + c + 0] = v4.x; Qs[r * 65 + c + 1] = v4.y;
        Qs[r * 65 + c + 2] = v4.z; Qs[r * 65 + c + 3] = v4.w;
    }
    if (tid < 64) { sm_m[tid] = -1e30f; sm_l[tid] = 0.f; }

    float acc[4][4];
#pragma unroll
    for (int i = 0; i < 4; i++)
#pragma unroll
        for (int j = 0; j < 4; j++) acc[i][j] = 0.f;
    __syncthreads();

    const int ntiles = q0 / 64 + 1;
    for (int jt = 0; jt < ntiles; jt++) {
        const int j0 = jt * 64;
        // load K, V tiles
#pragma unroll
        for (int i = 0; i < 4; i++) {
            int r = ty + i * 16;
            int c = tx * 4;
            float4 k4 = *(const float4*)(kbase + (size_t)(j0 + r) * Dd + c);
            float4 v4 = *(const float4*)(vbase + (size_t)(j0 + r) * Dd + c);
            Ks[r * 65 + c + 0] = k4.x; Ks[r * 65 + c + 1] = k4.y;
            Ks[r * 65 + c + 2] = k4.z; Ks[r * 65 + c + 3] = k4.w;
            Vs[r * 65 + c + 0] = v4.x; Vs[r * 65 + c + 1] = v4.y;
            Vs[r * 65 + c + 2] = v4.z; Vs[r * 65 + c + 3] = v4.w;
        }
        __syncthreads();

        // S = Q K^T * SCALE
        float s[4][4];
#pragma unroll
        for (int i = 0; i < 4; i++)
#pragma unroll
            for (int j = 0; j < 4; j++) s[i][j] = 0.f;
#pragma unroll
        for (int d = 0; d < 64; d++) {
            float qa[4], kb[4];
#pragma unroll
            for (int i = 0; i < 4; i++) qa[i] = Qs[(ty + i * 16) * 65 + d];
#pragma unroll
            for (int j = 0; j < 4; j++) kb[j] = Ks[(tx + j * 16) * 65 + d];
#pragma unroll
            for (int i = 0; i < 4; i++)
#pragma unroll
                for (int j = 0; j < 4; j++)
                    s[i][j] = fmaf(qa[i], kb[j], s[i][j]);
        }
        const bool diag = (j0 == q0);
#pragma unroll
        for (int i = 0; i < 4; i++) {
            int r = ty + i * 16;
#pragma unroll
            for (int j = 0; j < 4; j++) {
                int c = tx + j * 16;
                float val = s[i][j] * SCALE_F;
                if (diag && c > r) val = -1e30f;
                Ss[r * 65 + c] = val;
            }
        }
        __syncthreads();

        // online softmax row pass
        if (tid < 64) {
            int r = tid;
            float mold = sm_m[r];
            float mt = -1e30f;
            for (int c = 0; c < 64; c++) mt = fmaxf(mt, Ss[r * 65 + c]);
            float mnew = fmaxf(mold, mt);
            float sc = __expf(mold - mnew);
            float sum = 0.f;
            for (int c = 0; c < 64; c++) {
                float e = __expf(Ss[r * 65 + c] - mnew);
                Ss[r * 65 + c] = e;
                sum += e;
            }
            sm_l[r] = sm_l[r] * sc + sum;
            sm_m[r] = mnew;
            sm_scale[r] = sc;
        }
        __syncthreads();

        // rescale O and accumulate P @ V
        float rs[4];
#pragma unroll
        for (int i = 0; i < 4; i++) rs[i] = sm_scale[ty + i * 16];
#pragma unroll
        for (int i = 0; i < 4; i++)
#pragma unroll
            for (int j = 0; j < 4; j++) acc[i][j] *= rs[i];

#pragma unroll
        for (int kk = 0; kk < 64; kk++) {
            float pa[4], vb[4];
#pragma unroll
            for (int i = 0; i < 4; i++) pa[i] = Ss[(ty + i * 16) * 65 + kk];
#pragma unroll
            for (int j = 0; j < 4; j++) vb[j] = Vs[kk * 65 + tx + j * 16];
#pragma unroll
            for (int i = 0; i < 4; i++)
#pragma unroll
                for (int j = 0; j < 4; j++)
                    acc[i][j] = fmaf(pa[i], vb[j], acc[i][j]);
        }
        __syncthreads();
    }

    float invl[4];
#pragma unroll
    for (int i = 0; i < 4; i++) invl[i] = 1.0f / sm_l[ty + i * 16];

    float* obase = g_o + (size_t)(b * Tt) * Dd + h * HDd;
#pragma unroll
    for (int i = 0; i < 4; i++) {
        int r = q0 + ty + i * 16;
#pragma unroll
        for (int j = 0; j < 4; j++) {
            int c = tx + j * 16;
            obase[(size_t)r * Dd + c] = acc[i][j] * invl[i];
        }
    }
}

// ---------------- KNN memory attention + gate + bf16 round-trip -----------------
// grid: (T, B), 512 threads = 16 warps; warp h handles head h; lane covers 2 dims.
__global__ __launch_bounds__(512) void memcomb_kernel(
    const float* __restrict__ mem_bank, const int* __restrict__ knn_idx,
    const float* __restrict__ gate_bias)
{
    const int t = blockIdx.x, b = blockIdx.y;
    const int h = threadIdx.x >> 5;
    const int lane = threadIdx.x & 31;
    const int row = b * Tt + t;
    const int d0 = h * HDd + lane;
    const int d1 = d0 + 32;

    const float* qrow = g_q + (size_t)row * Dd;
    const float qa = qrow[d0], qb = qrow[d1];

    int idx[3];
#pragma unroll
    for (int kk = 0; kk < 3; kk++) idx[kk] = knn_idx[row * Kknn + kk];

    float dots[3];
#pragma unroll
    for (int kk = 0; kk < 3; kk++) {
        const float* mk = mem_bank + ((size_t)(b * Mm + idx[kk]) * 2) * Dd;
        float p = qa * mk[d0] + qb * mk[d1];
#pragma unroll
        for (int o = 16; o; o >>= 1) p += __shfl_xor_sync(0xffffffffu, p, o);
        dots[kk] = p * SCALE_F;
    }
    float m = fmaxf(dots[0], fmaxf(dots[1], dots[2]));
    float w[3];
    w[0] = __expf(dots[0] - m);
    w[1] = __expf(dots[1] - m);
    w[2] = __expf(dots[2] - m);
    float inv = 1.0f / (w[0] + w[1] + w[2]);
    w[0] *= inv; w[1] *= inv; w[2] *= inv;

    float oa = 0.f, ob = 0.f;
#pragma unroll
    for (int kk = 0; kk < 3; kk++) {
        const float* mv = mem_bank + ((size_t)(b * Mm + idx[kk]) * 2 + 1) * Dd;
        oa = fmaf(w[kk], mv[d0], oa);
        ob = fmaf(w[kk], mv[d1], ob);
    }

    const float g = gate_bias[h];
    float* orow = g_o + (size_t)row * Dd;
    float ca = oa * g + orow[d0] * (1.0f - g);
    float cb = ob * g + orow[d1] * (1.0f - g);
    ca = __bfloat162float(__float2bfloat16(ca));
    cb = __bfloat162float(__float2bfloat16(cb));
    orow[d0] = ca;
    orow[d1] = cb;
}

// -------------------------------- launch ----------------------------------------
extern "C" void kernel_launch(void* const* d_in, const int* in_sizes, int n_in,
                              void* d_out, int out_size)
{
    const float* x    = (const float*)d_in[0];
    const float* Wq   = (const float*)d_in[1];
    const float* bq   = (const float*)d_in[2];
    const float* Wk   = (const float*)d_in[3];
    const float* bk   = (const float*)d_in[4];
    const float* Wv   = (const float*)d_in[5];
    const float* bv   = (const float*)d_in[6];
    const float* Wo   = (const float*)d_in[7];
    const float* bo   = (const float*)d_in[8];
    const float* gate = (const float*)d_in[9];
    const float* mem  = (const float*)d_in[10];
    const int*   knn  = (const int*)d_in[11];
    float* out = (float*)d_out;

    float *q, *k, *v, *o;
    cudaGetSymbolAddress((void**)&q, g_q);
    cudaGetSymbolAddress((void**)&k, g_k);
    cudaGetSymbolAddress((void**)&v, g_v);
    cudaGetSymbolAddress((void**)&o, g_o);

    // 1) fused QKV projection
    {
        dim3 grid(Dd / 128, Nn / 128, 3);
        gemm3_kernel<<<grid, 256>>>(x, Wq, bq, q, Wk, bk, k, Wv, bv, v);
    }
    // 2) normalize q, k rows
    {
        dim3 grid(Nn, 2);
        normalize_kernel<<<grid, 256>>>();
    }
    // 3) causal flash attention
    {
        static const int smem_bytes = 4 * 64 * 65 * (int)sizeof(float);
        cudaFuncSetAttribute(attn_kernel,
                             cudaFuncAttributeMaxDynamicSharedMemorySize, smem_bytes);
        dim3 grid(Tt / 64, Hh, Bb);
        attn_kernel<<<grid, 256, smem_bytes>>>();
    }
    // 4) KNN memory attention + gate + bf16 round-trip (in place on g_o)
    {
        dim3 grid(Tt, Bb);
        memcomb_kernel<<<grid, 512>>>(mem, knn, gate);
    }
    // 5) output projection -> d_out
    {
        dim3 grid(Dd / 128, Nn / 128, 1);
        gemm3_kernel<<<grid, 256>>>(o, Wo, bo, out, Wo, bo, out, Wo, bo, out);
    }
}

// round 2
// speedup vs baseline: 1.8375x; 1.8375x over previous
#include <cuda_runtime.h>
#include <cuda_bf16.h>
#include <math.h>
#include <stdint.h>

#define Bb 2
#define Tt 2048
#define Dd 1024
#define Hh 16
#define Kknn 3
#define Mm 16384
#define HDd 64
#define Nn (Bb*Tt)          // 4096 rows
#define SCALE_F 4096.0f     // D * sqrt(H)

// ---------------- scratch (device globals; no allocation allowed) ----------------
__device__ float g_q[Nn*Dd];
__device__ float g_k[Nn*Dd];
__device__ float g_v[Nn*Dd];
__device__ float g_o[Nn*Dd];

// ================= helpers: tf32 mma + 3xTF32 split + fast exp ===================
__device__ __forceinline__ void mma_tf32(float* c, const uint32_t* a, const uint32_t* b)
{
    asm volatile(
        "mma.sync.aligned.m16n8k8.row.col.f32.tf32.tf32.f32 "
        "{%0,%1,%2,%3}, {%4,%5,%6,%7}, {%8,%9}, {%0,%1,%2,%3};\n"
        : "+f"(c[0]), "+f"(c[1]), "+f"(c[2]), "+f"(c[3])
        : "r"(a[0]), "r"(a[1]), "r"(a[2]), "r"(a[3]), "r"(b[0]), "r"(b[1]));
}

__device__ __forceinline__ void split3(float x, uint32_t& h, uint32_t& l)
{
    uint32_t xh = __float_as_uint(x) & 0xffffe000u;
    h = xh;
    l = __float_as_uint(x - __uint_as_float(xh));
}

// e^x via exp2 poly on the FMA pipe (no MUFU). Accurate to ~3e-6 rel.
__device__ __forceinline__ float fexp(float x)
{
    float t = x * 1.4426950408889634f;
    t = fmaxf(t, -126.0f);
    float r = rintf(t);
    float f = t - r;            // [-0.5, 0.5]
    float p = 0.0013333558146428443f;
    p = fmaf(p, f, 0.009618129107628477f);
    p = fmaf(p, f, 0.05550410866482158f);
    p = fmaf(p, f, 0.2402265069591007f);
    p = fmaf(p, f, 0.6931471805599453f);
    p = fmaf(p, f, 1.0f);
    int e = (int)r;
    float s = __int_as_float((e + 127) << 23);
    return s * p;
}

// ================= GEMM: C[n,m] = sum_k A[n,k]*W[m,k] + bias[m] ==================
// 3xTF32 mma. Block 128x128, BK=32, 256 threads (8 warps: 4x2), warp tile 32x64.
#define GLDA 36   // padded smem stride (floats): bank = (4*row + k) % 32, conflict-free

__global__ __launch_bounds__(256) void gemm_tf32_kernel(
    const float* __restrict__ A,
    const float* __restrict__ W0, const float* __restrict__ b0, float* __restrict__ C0,
    const float* __restrict__ W1, const float* __restrict__ b1, float* __restrict__ C1,
    const float* __restrict__ W2, const float* __restrict__ b2, float* __restrict__ C2)
{
    const float* W; const float* bias; float* C;
    if (blockIdx.z == 0)      { W = W0; bias = b0; C = C0; }
    else if (blockIdx.z == 1) { W = W1; bias = b1; C = C1; }
    else                      { W = W2; bias = b2; C = C2; }

    __shared__ float As[128][GLDA];
    __shared__ float Bs[128][GLDA];

    const int tid  = threadIdx.x;
    const int wid  = tid >> 5, lane = tid & 31;
    const int wm   = wid >> 1;      // 0..3
    const int wn   = wid & 1;       // 0..1
    const int g    = lane >> 2;     // 0..7
    const int tg   = lane & 3;      // 0..3
    const int row0 = blockIdx.y * 128;
    const int col0 = blockIdx.x * 128;

    // loader: thread t reads float4 at (row lm+32p, k = lk..lk+3)
    const int lm = tid >> 3;         // 0..31
    const int lk = (tid & 7) * 4;    // 0..28
    const float* Ag = A + (size_t)(row0 + lm) * Dd + lk;
    const float* Wg = W + (size_t)(col0 + lm) * Dd + lk;

    float4 pa[4], pb[4];
#pragma unroll
    for (int p = 0; p < 4; p++) {
        pa[p] = *(const float4*)(Ag + (size_t)p * 32 * Dd);
        pb[p] = *(const float4*)(Wg + (size_t)p * 32 * Dd);
    }

    float acc[2][8][4];
#pragma unroll
    for (int mt = 0; mt < 2; mt++)
#pragma unroll
        for (int nt = 0; nt < 8; nt++)
#pragma unroll
            for (int r = 0; r < 4; r++) acc[mt][nt][r] = 0.f;

    for (int kt = 0; kt < Dd / 32; kt++) {
#pragma unroll
        for (int p = 0; p < 4; p++) {
            *(float4*)&As[lm + 32 * p][lk] = pa[p];
            *(float4*)&Bs[lm + 32 * p][lk] = pb[p];
        }
        __syncthreads();
        if (kt < Dd / 32 - 1) {
            const int ko = (kt + 1) * 32;
#pragma unroll
            for (int p = 0; p < 4; p++) {
                pa[p] = *(const float4*)(Ag + (size_t)p * 32 * Dd + ko);
                pb[p] = *(const float4*)(Wg + (size_t)p * 32 * Dd + ko);
            }
        }
#pragma unroll
        for (int ks = 0; ks < 4; ks++) {
            const int k = ks * 8;
            uint32_t ah[2][4], al[2][4];
#pragma unroll
            for (int mt = 0; mt < 2; mt++) {
                const int m = wm * 32 + mt * 16;
                split3(As[m + g    ][k + tg    ], ah[mt][0], al[mt][0]);
                split3(As[m + g + 8][k + tg    ], ah[mt][1], al[mt][1]);
                split3(As[m + g    ][k + tg + 4], ah[mt][2], al[mt][2]);
                split3(As[m + g + 8][k + tg + 4], ah[mt][3], al[mt][3]);
            }
#pragma unroll
            for (int nt = 0; nt < 8; nt++) {
                const int n = wn * 64 + nt * 8 + g;
                uint32_t bh[2], bl[2];
                split3(Bs[n][k + tg    ], bh[0], bl[0]);
                split3(Bs[n][k + tg + 4], bh[1], bl[1]);
#pragma unroll
                for (int mt = 0; mt < 2; mt++) {
                    mma_tf32(acc[mt][nt], al[mt], bh);
                    mma_tf32(acc[mt][nt], ah[mt], bl);
                    mma_tf32(acc[mt][nt], ah[mt], bh);
                }
            }
        }
        __syncthreads();
    }

#pragma unroll
    for (int mt = 0; mt < 2; mt++) {
        const int r = row0 + wm * 32 + mt * 16 + g;
#pragma unroll
        for (int nt = 0; nt < 8; nt++) {
            const int c = col0 + wn * 64 + nt * 8 + tg * 2;
            const float bb0 = bias[c], bb1 = bias[c + 1];
            float2 v0 = make_float2(acc[mt][nt][0] + bb0, acc[mt][nt][1] + bb1);
            float2 v1 = make_float2(acc[mt][nt][2] + bb0, acc[mt][nt][3] + bb1);
            *(float2*)&C[(size_t)r * Dd + c]       = v0;
            *(float2*)&C[(size_t)(r + 8) * Dd + c] = v1;
        }
    }
}

// ---------------- row L2-normalize over D (q and k, in place) --------------------
__global__ __launch_bounds__(256) void normalize_kernel()
{
    const int row = blockIdx.x;
    float* buf = (blockIdx.y == 0) ? g_q : g_k;
    float* p = buf + (size_t)row * Dd;
    const int tid = threadIdx.x;

    float4 v = *(float4*)(p + tid * 4);
    float ss = v.x * v.x + v.y * v.y + v.z * v.z + v.w * v.w;
#pragma unroll
    for (int o = 16; o; o >>= 1) ss += __shfl_xor_sync(0xffffffffu, ss, o);

    __shared__ float ws[8];
    if ((tid & 31) == 0) ws[tid >> 5] = ss;
    __syncthreads();
    __shared__ float s_inv;
    if (tid == 0) {
        float s = 0.f;
#pragma unroll
        for (int i = 0; i < 8; i++) s += ws[i];
        s_inv = 1.0f / fmaxf(sqrtf(s), 1e-12f);
    }
    __syncthreads();
    float inv = s_inv;
    v.x *= inv; v.y *= inv; v.z *= inv; v.w *= inv;
    *(float4*)(p + tid * 4) = v;
}

// ================= causal flash attention, 3xTF32 mma + fast softmax =============
// grid (T/64, H, B), 256 threads (8 warps: wm=wid>>1 rows, wn=wid&1 cols).
#define ALD 68   // padded smem stride (floats)

__global__ __launch_bounds__(256) void attn_kernel()
{
    extern __shared__ float smem[];
    float* Qs = smem;               // 64 x 68
    float* Ks = Qs + 64 * ALD;
    float* Vs = Ks + 64 * ALD;
    float* Ss = Vs + 64 * ALD;
    __shared__ float sm_m[64], sm_l[64], sm_scale[64];

    const int q0 = blockIdx.x * 64;
    const int h  = blockIdx.y;
    const int b  = blockIdx.z;
    const int tid = threadIdx.x;
    const int wid = tid >> 5, lane = tid & 31;
    const int wm = wid >> 1, wn = wid & 1;
    const int g = lane >> 2, tg = lane & 3;
    const int ty = tid >> 4, tx = tid & 15;

    const float* qbase = g_q + (size_t)(b * Tt) * Dd + h * HDd;
    const float* kbase = g_k + (size_t)(b * Tt) * Dd + h * HDd;
    const float* vbase = g_v + (size_t)(b * Tt) * Dd + h * HDd;

#pragma unroll
    for (int i = 0; i < 4; i++) {
        int r = ty + i * 16;
        float4 v4 = *(const float4*)(qbase + (size_t)(q0 + r) * Dd + tx * 4);
        *(float4*)&Qs[r * ALD + tx * 4] = v4;
    }
    if (tid < 64) { sm_m[tid] = -1e30f; sm_l[tid] = 0.f; }

    float acc[4][4];
#pragma unroll
    for (int nt = 0; nt < 4; nt++)
#pragma unroll
        for (int r = 0; r < 4; r++) acc[nt][r] = 0.f;
    __syncthreads();

    const int ntiles = q0 / 64 + 1;
    for (int jt = 0; jt < ntiles; jt++) {
        const int j0 = jt * 64;
#pragma unroll
        for (int i = 0; i < 4; i++) {
            int r = ty + i * 16;
            float4 k4 = *(const float4*)(kbase + (size_t)(j0 + r) * Dd + tx * 4);
            float4 v4 = *(const float4*)(vbase + (size_t)(j0 + r) * Dd + tx * 4);
            *(float4*)&Ks[r * ALD + tx * 4] = k4;
            *(float4*)&Vs[r * ALD + tx * 4] = v4;
        }
        __syncthreads();

        // ---- S = Q K^T (3xTF32 mma) ----
        float sfr[4][4];
#pragma unroll
        for (int nt = 0; nt < 4; nt++)
#pragma unroll
            for (int r = 0; r < 4; r++) sfr[nt][r] = 0.f;

#pragma unroll
        for (int ks = 0; ks < 8; ks++) {
            const int k = ks * 8;
            const int m = wm * 16;
            uint32_t ah[4], al[4];
            split3(Qs[(m + g    ) * ALD + k + tg    ], ah[0], al[0]);
            split3(Qs[(m + g + 8) * ALD + k + tg    ], ah[1], al[1]);
            split3(Qs[(m + g    ) * ALD + k + tg + 4], ah[2], al[2]);
            split3(Qs[(m + g + 8) * ALD + k + tg + 4], ah[3], al[3]);
#pragma unroll
            for (int nt = 0; nt < 4; nt++) {
                const int n = wn * 32 + nt * 8 + g;
                uint32_t bh[2], bl[2];
                split3(Ks[n * ALD + k + tg    ], bh[0], bl[0]);
                split3(Ks[n * ALD + k + tg + 4], bh[1], bl[1]);
                mma_tf32(sfr[nt], al, bh);
                mma_tf32(sfr[nt], ah, bl);
                mma_tf32(sfr[nt], ah, bh);
            }
        }

        // ---- store S (scaled + causal mask) ----
        const bool diag = (j0 == q0);
        const int rr = wm * 16 + g;
#pragma unroll
        for (int nt = 0; nt < 4; nt++) {
            const int c = wn * 32 + nt * 8 + tg * 2;
            float v0 = sfr[nt][0] * SCALE_F, v1 = sfr[nt][1] * SCALE_F;
            float v2 = sfr[nt][2] * SCALE_F, v3 = sfr[nt][3] * SCALE_F;
            if (diag) {
                if (c     > rr    ) v0 = -1e30f;
                if (c + 1 > rr    ) v1 = -1e30f;
                if (c     > rr + 8) v2 = -1e30f;
                if (c + 1 > rr + 8) v3 = -1e30f;
            }
            Ss[ rr      * ALD + c] = v0; Ss[ rr      * ALD + c + 1] = v1;
            Ss[(rr + 8) * ALD + c] = v2; Ss[(rr + 8) * ALD + c + 1] = v3;
        }
        __syncthreads();

        // ---- softmax: quad-per-row, fast exp ----
        {
            const int r = tid >> 2, qd = tid & 3;
            float* rowp = &Ss[r * ALD + qd * 16];
            float4 x0 = ((float4*)rowp)[0];
            float4 x1 = ((float4*)rowp)[1];
            float4 x2 = ((float4*)rowp)[2];
            float4 x3 = ((float4*)rowp)[3];
            float mt = fmaxf(fmaxf(fmaxf(x0.x, x0.y), fmaxf(x0.z, x0.w)),
                      fmaxf(fmaxf(fmaxf(x1.x, x1.y), fmaxf(x1.z, x1.w)),
                      fmaxf(fmaxf(fmaxf(x2.x, x2.y), fmaxf(x2.z, x2.w)),
                            fmaxf(fmaxf(x3.x, x3.y), fmaxf(x3.z, x3.w)))));
            mt = fmaxf(mt, __shfl_xor_sync(0xffffffffu, mt, 1));
            mt = fmaxf(mt, __shfl_xor_sync(0xffffffffu, mt, 2));
            const float mprev = sm_m[r];
            const float mnew = fmaxf(mprev, mt);
            x0.x = fexp(x0.x - mnew); x0.y = fexp(x0.y - mnew);
            x0.z = fexp(x0.z - mnew); x0.w = fexp(x0.w - mnew);
            x1.x = fexp(x1.x - mnew); x1.y = fexp(x1.y - mnew);
            x1.z = fexp(x1.z - mnew); x1.w = fexp(x1.w - mnew);
            x2.x = fexp(x2.x - mnew); x2.y = fexp(x2.y - mnew);
            x2.z = fexp(x2.z - mnew); x2.w = fexp(x2.w - mnew);
            x3.x = fexp(x3.x - mnew); x3.y = fexp(x3.y - mnew);
            x3.z = fexp(x3.z - mnew); x3.w = fexp(x3.w - mnew);
            float sum = (x0.x + x0.y + x0.z + x0.w) + (x1.x + x1.y + x1.z + x1.w)
                      + (x2.x + x2.y + x2.z + x2.w) + (x3.x + x3.y + x3.z + x3.w);
            ((float4*)rowp)[0] = x0; ((float4*)rowp)[1] = x1;
            ((float4*)rowp)[2] = x2; ((float4*)rowp)[3] = x3;
            sum += __shfl_xor_sync(0xffffffffu, sum, 1);
            sum += __shfl_xor_sync(0xffffffffu, sum, 2);
            if (qd == 0) {
                const float sc = fexp(mprev - mnew);
                sm_scale[r] = sc;
                sm_l[r] = sm_l[r] * sc + sum;
                sm_m[r] = mnew;
            }
        }
        __syncthreads();

        // ---- rescale O accum, then O += P V (3xTF32 mma) ----
        {
            const float s0 = sm_scale[wm * 16 + g];
            const float s1 = sm_scale[wm * 16 + 8 + g];
#pragma unroll
            for (int nt = 0; nt < 4; nt++) {
                acc[nt][0] *= s0; acc[nt][1] *= s0;
                acc[nt][2] *= s1; acc[nt][3] *= s1;
            }
        }
#pragma unroll
        for (int ks = 0; ks < 8; ks++) {
            const int k = ks * 8;
            const int m = wm * 16;
            uint32_t ah[4], al[4];
            split3(Ss[(m + g    ) * ALD + k + tg    ], ah[0], al[0]);
            split3(Ss[(m + g + 8) * ALD + k + tg    ], ah[1], al[1]);
            split3(Ss[(m + g    ) * ALD + k + tg + 4], ah[2], al[2]);
            split3(Ss[(m + g + 8) * ALD + k + tg + 4], ah[3], al[3]);
#pragma unroll
            for (int nt = 0; nt < 4; nt++) {
                const int n = wn * 32 + nt * 8 + g;
                uint32_t bh[2], bl[2];
                split3(Vs[(k + tg    ) * ALD + n], bh[0], bl[0]);
                split3(Vs[(k + tg + 4) * ALD + n], bh[1], bl[1]);
                mma_tf32(acc[nt], al, bh);
                mma_tf32(acc[nt], ah, bl);
                mma_tf32(acc[nt], ah, bh);
            }
        }
        __syncthreads();
    }

    // ---- epilogue: normalize by l, write to g_o ----
    const float i0 = 1.0f / sm_l[wm * 16 + g];
    const float i1 = 1.0f / sm_l[wm * 16 + 8 + g];
    float* obase = g_o + (size_t)(b * Tt) * Dd + h * HDd;
    const int r = q0 + wm * 16 + g;
#pragma unroll
    for (int nt = 0; nt < 4; nt++) {
        const int c = wn * 32 + nt * 8 + tg * 2;
        float2 v0 = make_float2(acc[nt][0] * i0, acc[nt][1] * i0);
        float2 v1 = make_float2(acc[nt][2] * i1, acc[nt][3] * i1);
        *(float2*)&obase[(size_t)r * Dd + c]       = v0;
        *(float2*)&obase[(size_t)(r + 8) * Dd + c] = v1;
    }
}

// ---------------- KNN memory attention + gate + bf16 round-trip -----------------
__global__ __launch_bounds__(512) void memcomb_kernel(
    const float* __restrict__ mem_bank, const int* __restrict__ knn_idx,
    const float* __restrict__ gate_bias)
{
    const int t = blockIdx.x, b = blockIdx.y;
    const int h = threadIdx.x >> 5;
    const int lane = threadIdx.x & 31;
    const int row = b * Tt + t;
    const int d0 = h * HDd + lane;
    const int d1 = d0 + 32;

    const float* qrow = g_q + (size_t)row * Dd;
    const float qa = qrow[d0], qb = qrow[d1];

    int idx[3];
#pragma unroll
    for (int kk = 0; kk < 3; kk++) idx[kk] = knn_idx[row * Kknn + kk];

    float dots[3];
#pragma unroll
    for (int kk = 0; kk < 3; kk++) {
        const float* mk = mem_bank + ((size_t)(b * Mm + idx[kk]) * 2) * Dd;
        float p = qa * mk[d0] + qb * mk[d1];
#pragma unroll
        for (int o = 16; o; o >>= 1) p += __shfl_xor_sync(0xffffffffu, p, o);
        dots[kk] = p * SCALE_F;
    }
    float m = fmaxf(dots[0], fmaxf(dots[1], dots[2]));
    float w[3];
    w[0] = __expf(dots[0] - m);
    w[1] = __expf(dots[1] - m);
    w[2] = __expf(dots[2] - m);
    float inv = 1.0f / (w[0] + w[1] + w[2]);
    w[0] *= inv; w[1] *= inv; w[2] *= inv;

    float oa = 0.f, ob = 0.f;
#pragma unroll
    for (int kk = 0; kk < 3; kk++) {
        const float* mv = mem_bank + ((size_t)(b * Mm + idx[kk]) * 2 + 1) * Dd;
        oa = fmaf(w[kk], mv[d0], oa);
        ob = fmaf(w[kk], mv[d1], ob);
    }

    const float gbv = gate_bias[h];
    float* orow = g_o + (size_t)row * Dd;
    float ca = oa * gbv + orow[d0] * (1.0f - gbv);
    float cb = ob * gbv + orow[d1] * (1.0f - gbv);
    ca = __bfloat162float(__float2bfloat16(ca));
    cb = __bfloat162float(__float2bfloat16(cb));
    orow[d0] = ca;
    orow[d1] = cb;
}

// -------------------------------- launch ----------------------------------------
extern "C" void kernel_launch(void* const* d_in, const int* in_sizes, int n_in,
                              void* d_out, int out_size)
{
    const float* x    = (const float*)d_in[0];
    const float* Wq   = (const float*)d_in[1];
    const float* bq   = (const float*)d_in[2];
    const float* Wk   = (const float*)d_in[3];
    const float* bk   = (const float*)d_in[4];
    const float* Wv   = (const float*)d_in[5];
    const float* bv   = (const float*)d_in[6];
    const float* Wo   = (const float*)d_in[7];
    const float* bo   = (const float*)d_in[8];
    const float* gate = (const float*)d_in[9];
    const float* mem  = (const float*)d_in[10];
    const int*   knn  = (const int*)d_in[11];
    float* out = (float*)d_out;

    float *q, *k, *v, *o;
    cudaGetSymbolAddress((void**)&q, g_q);
    cudaGetSymbolAddress((void**)&k, g_k);
    cudaGetSymbolAddress((void**)&v, g_v);
    cudaGetSymbolAddress((void**)&o, g_o);

    // 1) fused QKV projection (3xTF32 mma)
    {
        dim3 grid(Dd / 128, Nn / 128, 3);
        gemm_tf32_kernel<<<grid, 256>>>(x, Wq, bq, q, Wk, bk, k, Wv, bv, v);
    }
    // 2) normalize q, k rows
    {
        dim3 grid(Nn, 2);
        normalize_kernel<<<grid, 256>>>();
    }
    // 3) causal flash attention (3xTF32 mma + fast softmax)
    {
        const int smem_bytes = 4 * 64 * ALD * (int)sizeof(float);
        cudaFuncSetAttribute(attn_kernel,
                             cudaFuncAttributeMaxDynamicSharedMemorySize, smem_bytes);
        dim3 grid(Tt / 64, Hh, Bb);
        attn_kernel<<<grid, 256, smem_bytes>>>();
    }
    // 4) KNN memory attention + gate + bf16 round-trip (in place on g_o)
    {
        dim3 grid(Tt, Bb);
        memcomb_kernel<<<grid, 512>>>(mem, knn, gate);
    }
    // 5) output projection -> d_out (3xTF32 mma)
    {
        dim3 grid(Dd / 128, Nn / 128, 1);
        gemm_tf32_kernel<<<grid, 256>>>(o, Wo, bo, out, Wo, bo, out, Wo, bo, out);
    }
}

// round 8
// speedup vs baseline: 1.8622x; 1.0134x over previous
#include <cuda_runtime.h>
#include <cuda_bf16.h>
#include <math.h>
#include <stdint.h>

#define Bb 2
#define Tt 2048
#define Dd 1024
#define Hh 16
#define Kknn 3
#define Mm 16384
#define HDd 64
#define Nn (Bb*Tt)          // 4096 rows
#define SCALE_F 4096.0f     // D * sqrt(H)

// ---------------- scratch (device globals; no allocation allowed) ----------------
__device__ float g_q[Nn*Dd];
__device__ float g_k[Nn*Dd];
__device__ float g_v[Nn*Dd];
__device__ float g_o[Nn*Dd];
__device__ __nv_bfloat16 g_obf[Nn*Dd];     // combined, exact bf16
__device__ __nv_bfloat16 g_xh[Nn*Dd];      // x split hi/lo
__device__ __nv_bfloat16 g_xl[Nn*Dd];
__device__ __nv_bfloat16 g_wvh[Dd*Dd];
__device__ __nv_bfloat16 g_wvl[Dd*Dd];
__device__ __nv_bfloat16 g_woh[Dd*Dd];
__device__ __nv_bfloat16 g_wol[Dd*Dd];

// ================= helpers ===================
__device__ __forceinline__ void mma_tf32(float* c, const uint32_t* a, const uint32_t* b)
{
    asm volatile(
        "mma.sync.aligned.m16n8k8.row.col.f32.tf32.tf32.f32 "
        "{%0,%1,%2,%3}, {%4,%5,%6,%7}, {%8,%9}, {%0,%1,%2,%3};\n"
        : "+f"(c[0]), "+f"(c[1]), "+f"(c[2]), "+f"(c[3])
        : "r"(a[0]), "r"(a[1]), "r"(a[2]), "r"(a[3]), "r"(b[0]), "r"(b[1]));
}

__device__ __forceinline__ void mma_bf16(float* c, const uint32_t* a, const uint32_t* b)
{
    asm volatile(
        "mma.sync.aligned.m16n8k16.row.col.f32.bf16.bf16.f32 "
        "{%0,%1,%2,%3}, {%4,%5,%6,%7}, {%8,%9}, {%0,%1,%2,%3};\n"
        : "+f"(c[0]), "+f"(c[1]), "+f"(c[2]), "+f"(c[3])
        : "r"(a[0]), "r"(a[1]), "r"(a[2]), "r"(a[3]), "r"(b[0]), "r"(b[1]));
}

__device__ __forceinline__ void split3(float x, uint32_t& h, uint32_t& l)
{
    uint32_t xh = __float_as_uint(x) & 0xffffe000u;
    h = xh;
    l = __float_as_uint(x - __uint_as_float(xh));
}

// pack two floats to bf16x2 (elem0 in low half)
__device__ __forceinline__ uint32_t pack_bf16(float e0, float e1)
{
    uint32_t r;
    asm("cvt.rn.bf16x2.f32 %0, %1, %2;" : "=r"(r) : "f"(e1), "f"(e0));
    return r;
}

// e^x via exp2 poly on the FMA pipe (no MUFU). Accurate to ~3e-6 rel.
__device__ __forceinline__ float fexp(float x)
{
    float t = x * 1.4426950408889634f;
    t = fmaxf(t, -126.0f);
    float r = rintf(t);
    float f = t - r;
    float p = 0.0013333558146428443f;
    p = fmaf(p, f, 0.009618129107628477f);
    p = fmaf(p, f, 0.05550410866482158f);
    p = fmaf(p, f, 0.2402265069591007f);
    p = fmaf(p, f, 0.6931471805599453f);
    p = fmaf(p, f, 1.0f);
    int e = (int)r;
    float s = __int_as_float((e + 127) << 23);
    return s * p;
}

// ---------------- split fp32 -> bf16 hi + bf16 lo ----------------
__global__ __launch_bounds__(256) void split_kernel(
    const float* __restrict__ src, __nv_bfloat16* __restrict__ dh,
    __nv_bfloat16* __restrict__ dl, int n4)
{
    int i = blockIdx.x * 256 + threadIdx.x;
    if (i >= n4) return;
    float4 v = ((const float4*)src)[i];
    uint32_t h0 = pack_bf16(v.x, v.y);
    uint32_t h1 = pack_bf16(v.z, v.w);
    float fx = __uint_as_float(h0 << 16);
    float fy = __uint_as_float(h0 & 0xffff0000u);
    float fz = __uint_as_float(h1 << 16);
    float fw = __uint_as_float(h1 & 0xffff0000u);
    uint32_t l0 = pack_bf16(v.x - fx, v.y - fy);
    uint32_t l1 = pack_bf16(v.z - fz, v.w - fw);
    ((uint2*)dh)[i] = make_uint2(h0, h1);
    ((uint2*)dl)[i] = make_uint2(l0, l1);
}

// ================= GEMM (3xTF32): used for Q, K projections ======================
#define GLDA 36

__global__ __launch_bounds__(256) void gemm_tf32_kernel(
    const float* __restrict__ A,
    const float* __restrict__ W0, const float* __restrict__ b0, float* __restrict__ C0,
    const float* __restrict__ W1, const float* __restrict__ b1, float* __restrict__ C1)
{
    const float* W; const float* bias; float* C;
    if (blockIdx.z == 0) { W = W0; bias = b0; C = C0; }
    else                 { W = W1; bias = b1; C = C1; }

    __shared__ float As[128][GLDA];
    __shared__ float Bs[128][GLDA];

    const int tid  = threadIdx.x;
    const int wid  = tid >> 5, lane = tid & 31;
    const int wm   = wid >> 1;
    const int wn   = wid & 1;
    const int g    = lane >> 2;
    const int tg   = lane & 3;
    const int row0 = blockIdx.y * 128;
    const int col0 = blockIdx.x * 128;

    const int lm = tid >> 3;
    const int lk = (tid & 7) * 4;
    const float* Ag = A + (size_t)(row0 + lm) * Dd + lk;
    const float* Wg = W + (size_t)(col0 + lm) * Dd + lk;

    float4 pa[4], pb[4];
#pragma unroll
    for (int p = 0; p < 4; p++) {
        pa[p] = *(const float4*)(Ag + (size_t)p * 32 * Dd);
        pb[p] = *(const float4*)(Wg + (size_t)p * 32 * Dd);
    }

    float acc[2][8][4];
#pragma unroll
    for (int mt = 0; mt < 2; mt++)
#pragma unroll
        for (int nt = 0; nt < 8; nt++)
#pragma unroll
            for (int r = 0; r < 4; r++) acc[mt][nt][r] = 0.f;

    for (int kt = 0; kt < Dd / 32; kt++) {
#pragma unroll
        for (int p = 0; p < 4; p++) {
            *(float4*)&As[lm + 32 * p][lk] = pa[p];
            *(float4*)&Bs[lm + 32 * p][lk] = pb[p];
        }
        __syncthreads();
        if (kt < Dd / 32 - 1) {
            const int ko = (kt + 1) * 32;
#pragma unroll
            for (int p = 0; p < 4; p++) {
                pa[p] = *(const float4*)(Ag + (size_t)p * 32 * Dd + ko);
                pb[p] = *(const float4*)(Wg + (size_t)p * 32 * Dd + ko);
            }
        }
#pragma unroll
        for (int ks = 0; ks < 4; ks++) {
            const int k = ks * 8;
            uint32_t ah[2][4], al[2][4];
#pragma unroll
            for (int mt = 0; mt < 2; mt++) {
                const int m = wm * 32 + mt * 16;
                split3(As[m + g    ][k + tg    ], ah[mt][0], al[mt][0]);
                split3(As[m + g + 8][k + tg    ], ah[mt][1], al[mt][1]);
                split3(As[m + g    ][k + tg + 4], ah[mt][2], al[mt][2]);
                split3(As[m + g + 8][k + tg + 4], ah[mt][3], al[mt][3]);
            }
#pragma unroll
            for (int nt = 0; nt < 8; nt++) {
                const int n = wn * 64 + nt * 8 + g;
                uint32_t bh[2], bl[2];
                split3(Bs[n][k + tg    ], bh[0], bl[0]);
                split3(Bs[n][k + tg + 4], bh[1], bl[1]);
#pragma unroll
                for (int mt = 0; mt < 2; mt++) {
                    mma_tf32(acc[mt][nt], al[mt], bh);
                    mma_tf32(acc[mt][nt], ah[mt], bl);
                    mma_tf32(acc[mt][nt], ah[mt], bh);
                }
            }
        }
        __syncthreads();
    }

#pragma unroll
    for (int mt = 0; mt < 2; mt++) {
        const int r = row0 + wm * 32 + mt * 16 + g;
#pragma unroll
        for (int nt = 0; nt < 8; nt++) {
            const int c = col0 + wn * 64 + nt * 8 + tg * 2;
            const float bb0 = bias[c], bb1 = bias[c + 1];
            float2 v0 = make_float2(acc[mt][nt][0] + bb0, acc[mt][nt][1] + bb1);
            float2 v1 = make_float2(acc[mt][nt][2] + bb0, acc[mt][nt][3] + bb1);
            *(float2*)&C[(size_t)r * Dd + c]       = v0;
            *(float2*)&C[(size_t)(r + 8) * Dd + c] = v1;
        }
    }
}

// ================= GEMM (bf16 pre-split planes): V proj (3x) & output proj (2x) ==
// C[n,m] = sum_k (Ah+Al)[n,k]*(Bh+Bl)[m,k] + bias[m], dropping Al*Bl (and Al*Bh
// when USE_AL=0, i.e. A exact in bf16).
#define BLDA 40   // bf16 elements per smem row

template<int USE_AL>
__global__ __launch_bounds__(256) void gemm_bf16_kernel(
    const __nv_bfloat16* __restrict__ Ah, const __nv_bfloat16* __restrict__ Al,
    const __nv_bfloat16* __restrict__ Bh, const __nv_bfloat16* __restrict__ Bl,
    const float* __restrict__ bias, float* __restrict__ C)
{
    __shared__ __align__(16) uint16_t sAh[128][BLDA];
    __shared__ __align__(16) uint16_t sAl[128][BLDA];
    __shared__ __align__(16) uint16_t sBh[128][BLDA];
    __shared__ __align__(16) uint16_t sBl[128][BLDA];

    const int tid  = threadIdx.x;
    const int wid  = tid >> 5, lane = tid & 31;
    const int wm   = wid >> 1;
    const int wn   = wid & 1;
    const int g    = lane >> 2;
    const int tg   = lane & 3;
    const int row0 = blockIdx.y * 128;
    const int col0 = blockIdx.x * 128;

    // loader: thread t covers row=t>>1, 16 bf16 at part*16
    const int lrow = tid >> 1;
    const int lpart = (tid & 1) * 16;
    const __nv_bfloat16* gAh = Ah + (size_t)(row0 + lrow) * Dd + lpart;
    const __nv_bfloat16* gAl = USE_AL ? (Al + (size_t)(row0 + lrow) * Dd + lpart) : gAh;
    const __nv_bfloat16* gBh = Bh + (size_t)(col0 + lrow) * Dd + lpart;
    const __nv_bfloat16* gBl = Bl + (size_t)(col0 + lrow) * Dd + lpart;

    uint4 pah[2], pal[2], pbh[2], pbl[2];
#pragma unroll
    for (int p = 0; p < 2; p++) {
        pah[p] = ((const uint4*)gAh)[p];
        if (USE_AL) pal[p] = ((const uint4*)gAl)[p];
        pbh[p] = ((const uint4*)gBh)[p];
        pbl[p] = ((const uint4*)gBl)[p];
    }

    float acc[2][8][4];
#pragma unroll
    for (int mt = 0; mt < 2; mt++)
#pragma unroll
        for (int nt = 0; nt < 8; nt++)
#pragma unroll
            for (int r = 0; r < 4; r++) acc[mt][nt][r] = 0.f;

    for (int kt = 0; kt < Dd / 32; kt++) {
#pragma unroll
        for (int p = 0; p < 2; p++) {
            *(uint4*)&sAh[lrow][lpart + p * 8] = pah[p];
            if (USE_AL) *(uint4*)&sAl[lrow][lpart + p * 8] = pal[p];
            *(uint4*)&sBh[lrow][lpart + p * 8] = pbh[p];
            *(uint4*)&sBl[lrow][lpart + p * 8] = pbl[p];
        }
        __syncthreads();
        if (kt < Dd / 32 - 1) {
            const int ko = (kt + 1) * 32;
#pragma unroll
            for (int p = 0; p < 2; p++) {
                pah[p] = ((const uint4*)(gAh + ko))[p];
                if (USE_AL) pal[p] = ((const uint4*)(gAl + ko))[p];
                pbh[p] = ((const uint4*)(gBh + ko))[p];
                pbl[p] = ((const uint4*)(gBl + ko))[p];
            }
        }
#pragma unroll
        for (int half = 0; half < 2; half++) {
            const int k = half * 16;
            uint32_t ah[2][4], al[2][4];
#pragma unroll
            for (int mt = 0; mt < 2; mt++) {
                const int m = wm * 32 + mt * 16;
                ah[mt][0] = *(const uint32_t*)&sAh[m + g    ][k + 2 * tg    ];
                ah[mt][1] = *(const uint32_t*)&sAh[m + 8 + g][k + 2 * tg    ];
                ah[mt][2] = *(const uint32_t*)&sAh[m + g    ][k + 2 * tg + 8];
                ah[mt][3] = *(const uint32_t*)&sAh[m + 8 + g][k + 2 * tg + 8];
                if (USE_AL) {
                    al[mt][0] = *(const uint32_t*)&sAl[m + g    ][k + 2 * tg    ];
                    al[mt][1] = *(const uint32_t*)&sAl[m + 8 + g][k + 2 * tg    ];
                    al[mt][2] = *(const uint32_t*)&sAl[m + g    ][k + 2 * tg + 8];
                    al[mt][3] = *(const uint32_t*)&sAl[m + 8 + g][k + 2 * tg + 8];
                }
            }
#pragma unroll
            for (int nt = 0; nt < 8; nt++) {
                const int n = wn * 64 + nt * 8 + g;
                uint32_t bh[2], bl[2];
                bh[0] = *(const uint32_t*)&sBh[n][k + 2 * tg    ];
                bh[1] = *(const uint32_t*)&sBh[n][k + 2 * tg + 8];
                bl[0] = *(const uint32_t*)&sBl[n][k + 2 * tg    ];
                bl[1] = *(const uint32_t*)&sBl[n][k + 2 * tg + 8];
#pragma unroll
                for (int mt = 0; mt < 2; mt++) {
                    mma_bf16(acc[mt][nt], ah[mt], bh);
                    mma_bf16(acc[mt][nt], ah[mt], bl);
                    if (USE_AL) mma_bf16(acc[mt][nt], al[mt], bh);
                }
            }
        }
        __syncthreads();
    }

#pragma unroll
    for (int mt = 0; mt < 2; mt++) {
        const int r = row0 + wm * 32 + mt * 16 + g;
#pragma unroll
        for (int nt = 0; nt < 8; nt++) {
            const int c = col0 + wn * 64 + nt * 8 + tg * 2;
            const float bb0 = bias[c], bb1 = bias[c + 1];
            float2 v0 = make_float2(acc[mt][nt][0] + bb0, acc[mt][nt][1] + bb1);
            float2 v1 = make_float2(acc[mt][nt][2] + bb0, acc[mt][nt][3] + bb1);
            *(float2*)&C[(size_t)r * Dd + c]       = v0;
            *(float2*)&C[(size_t)(r + 8) * Dd + c] = v1;
        }
    }
}

// ---------------- row L2-normalize over D (q and k, in place) --------------------
__global__ __launch_bounds__(256) void normalize_kernel()
{
    const int row = blockIdx.x;
    float* buf = (blockIdx.y == 0) ? g_q : g_k;
    float* p = buf + (size_t)row * Dd;
    const int tid = threadIdx.x;

    float4 v = *(float4*)(p + tid * 4);
    float ss = v.x * v.x + v.y * v.y + v.z * v.z + v.w * v.w;
#pragma unroll
    for (int o = 16; o; o >>= 1) ss += __shfl_xor_sync(0xffffffffu, ss, o);

    __shared__ float ws[8];
    if ((tid & 31) == 0) ws[tid >> 5] = ss;
    __syncthreads();
    __shared__ float s_inv;
    if (tid == 0) {
        float s = 0.f;
#pragma unroll
        for (int i = 0; i < 8; i++) s += ws[i];
        s_inv = 1.0f / fmaxf(sqrtf(s), 1e-12f);
    }
    __syncthreads();
    float inv = s_inv;
    v.x *= inv; v.y *= inv; v.z *= inv; v.w *= inv;
    *(float4*)(p + tid * 4) = v;
}

// ================= causal flash attention: QK^T 3xTF32, P·V bf16-3x ==============
#define ALD 68    // fp32 smem stride
#define PLD 72    // bf16 smem stride

__global__ __launch_bounds__(256) void attn_kernel()
{
    extern __shared__ float smem[];
    float* Qs = smem;                         // 64 x 68 fp32
    float* Ks = Qs + 64 * ALD;
    float* Ss = Ks + 64 * ALD;                // logits fp32
    uint16_t* Vh = (uint16_t*)(Ss + 64 * ALD);  // [n=64][k=72] bf16 (n-major!)
    uint16_t* Vl = Vh + 64 * PLD;
    uint16_t* Ph = Vl + 64 * PLD;               // [m=64][j=72] bf16
    uint16_t* Pl = Ph + 64 * PLD;
    __shared__ float sm_m[64], sm_l[64], sm_scale[64];

    const int q0 = blockIdx.x * 64;
    const int h  = blockIdx.y;
    const int b  = blockIdx.z;
    const int tid = threadIdx.x;
    const int wid = tid >> 5, lane = tid & 31;
    const int wm = wid >> 1, wn = wid & 1;
    const int g = lane >> 2, tg = lane & 3;
    const int ty = tid >> 4, tx = tid & 15;

    const float* qbase = g_q + (size_t)(b * Tt) * Dd + h * HDd;
    const float* kbase = g_k + (size_t)(b * Tt) * Dd + h * HDd;
    const float* vbase = g_v + (size_t)(b * Tt) * Dd + h * HDd;

#pragma unroll
    for (int i = 0; i < 4; i++) {
        int r = ty + i * 16;
        float4 v4 = *(const float4*)(qbase + (size_t)(q0 + r) * Dd + tx * 4);
        *(float4*)&Qs[r * ALD + tx * 4] = v4;
    }
    if (tid < 64) { sm_m[tid] = -1e30f; sm_l[tid] = 0.f; }

    float acc[4][4];
#pragma unroll
    for (int nt = 0; nt < 4; nt++)
#pragma unroll
        for (int r = 0; r < 4; r++) acc[nt][r] = 0.f;
    __syncthreads();

    const int ntiles = q0 / 64 + 1;
    for (int jt = 0; jt < ntiles; jt++) {
        const int j0 = jt * 64;
#pragma unroll
        for (int i = 0; i < 4; i++) {
            int r = ty + i * 16;          // token index within tile (= k of PV)
            float4 k4 = *(const float4*)(kbase + (size_t)(j0 + r) * Dd + tx * 4);
            *(float4*)&Ks[r * ALD + tx * 4] = k4;
            float4 v4 = *(const float4*)(vbase + (size_t)(j0 + r) * Dd + tx * 4);
            // split V into bf16 planes stored n-major: Vh[n][k]
            float vv[4] = {v4.x, v4.y, v4.z, v4.w};
#pragma unroll
            for (int c = 0; c < 4; c++) {
                int n = tx * 4 + c;
                float f = vv[c];
                __nv_bfloat16 hb = __float2bfloat16(f);
                float fh = __bfloat162float(hb);
                __nv_bfloat16 lb = __float2bfloat16(f - fh);
                Vh[n * PLD + r] = *(uint16_t*)&hb;
                Vl[n * PLD + r] = *(uint16_t*)&lb;
            }
        }
        __syncthreads();

        // ---- S = Q K^T (3xTF32 mma) ----
        float sfr[4][4];
#pragma unroll
        for (int nt = 0; nt < 4; nt++)
#pragma unroll
            for (int r = 0; r < 4; r++) sfr[nt][r] = 0.f;

#pragma unroll
        for (int ks = 0; ks < 8; ks++) {
            const int k = ks * 8;
            const int m = wm * 16;
            uint32_t ah[4], al[4];
            split3(Qs[(m + g    ) * ALD + k + tg    ], ah[0], al[0]);
            split3(Qs[(m + g + 8) * ALD + k + tg    ], ah[1], al[1]);
            split3(Qs[(m + g    ) * ALD + k + tg + 4], ah[2], al[2]);
            split3(Qs[(m + g + 8) * ALD + k + tg + 4], ah[3], al[3]);
#pragma unroll
            for (int nt = 0; nt < 4; nt++) {
                const int n = wn * 32 + nt * 8 + g;
                uint32_t bh[2], bl[2];
                split3(Ks[n * ALD + k + tg    ], bh[0], bl[0]);
                split3(Ks[n * ALD + k + tg + 4], bh[1], bl[1]);
                mma_tf32(sfr[nt], al, bh);
                mma_tf32(sfr[nt], ah, bl);
                mma_tf32(sfr[nt], ah, bh);
            }
        }

        // ---- store S (scaled + causal mask) ----
        const bool diag = (j0 == q0);
        const int rr = wm * 16 + g;
#pragma unroll
        for (int nt = 0; nt < 4; nt++) {
            const int c = wn * 32 + nt * 8 + tg * 2;
            float v0 = sfr[nt][0] * SCALE_F, v1 = sfr[nt][1] * SCALE_F;
            float v2 = sfr[nt][2] * SCALE_F, v3 = sfr[nt][3] * SCALE_F;
            if (diag) {
                if (c     > rr    ) v0 = -1e30f;
                if (c + 1 > rr    ) v1 = -1e30f;
                if (c     > rr + 8) v2 = -1e30f;
                if (c + 1 > rr + 8) v3 = -1e30f;
            }
            Ss[ rr      * ALD + c] = v0; Ss[ rr      * ALD + c + 1] = v1;
            Ss[(rr + 8) * ALD + c] = v2; Ss[(rr + 8) * ALD + c + 1] = v3;
        }
        __syncthreads();

        // ---- softmax: quad-per-row, fast exp, write bf16 hi/lo P planes ----
        {
            const int r = tid >> 2, qd = tid & 3;
            float* rowp = &Ss[r * ALD + qd * 16];
            float x[16];
#pragma unroll
            for (int j = 0; j < 4; j++) {
                float4 t4 = ((float4*)rowp)[j];
                x[4*j+0] = t4.x; x[4*j+1] = t4.y; x[4*j+2] = t4.z; x[4*j+3] = t4.w;
            }
            float mt = x[0];
#pragma unroll
            for (int j = 1; j < 16; j++) mt = fmaxf(mt, x[j]);
            mt = fmaxf(mt, __shfl_xor_sync(0xffffffffu, mt, 1));
            mt = fmaxf(mt, __shfl_xor_sync(0xffffffffu, mt, 2));
            const float mprev = sm_m[r];
            const float mnew = fmaxf(mprev, mt);
            float sum = 0.f;
#pragma unroll
            for (int j = 0; j < 16; j++) { x[j] = fexp(x[j] - mnew); sum += x[j]; }
            // write bf16 hi/lo pairs
#pragma unroll
            for (int pjj = 0; pjj < 8; pjj++) {
                float e0 = x[2*pjj], e1 = x[2*pjj+1];
                uint32_t hp = pack_bf16(e0, e1);
                float f0 = __uint_as_float(hp << 16);
                float f1 = __uint_as_float(hp & 0xffff0000u);
                uint32_t lp = pack_bf16(e0 - f0, e1 - f1);
                *(uint32_t*)&Ph[r * PLD + qd * 16 + 2 * pjj] = hp;
                *(uint32_t*)&Pl[r * PLD + qd * 16 + 2 * pjj] = lp;
            }
            sum += __shfl_xor_sync(0xffffffffu, sum, 1);
            sum += __shfl_xor_sync(0xffffffffu, sum, 2);
            if (qd == 0) {
                const float sc = fexp(mprev - mnew);
                sm_scale[r] = sc;
                sm_l[r] = sm_l[r] * sc + sum;
                sm_m[r] = mnew;
            }
        }
        __syncthreads();

        // ---- rescale O accum, then O += P V (bf16 3x mma) ----
        {
            const float s0 = sm_scale[wm * 16 + g];
            const float s1 = sm_scale[wm * 16 + 8 + g];
#pragma unroll
            for (int nt = 0; nt < 4; nt++) {
                acc[nt][0] *= s0; acc[nt][1] *= s0;
                acc[nt][2] *= s1; acc[nt][3] *= s1;
            }
        }
#pragma unroll
        for (int ks = 0; ks < 4; ks++) {
            const int kk = ks * 16;
            const int m = wm * 16;
            uint32_t ah[4], al[4];
            ah[0] = *(const uint32_t*)&Ph[(m + g    ) * PLD + kk + 2 * tg    ];
            ah[1] = *(const uint32_t*)&Ph[(m + 8 + g) * PLD + kk + 2 * tg    ];
            ah[2] = *(const uint32_t*)&Ph[(m + g    ) * PLD + kk + 2 * tg + 8];
            ah[3] = *(const uint32_t*)&Ph[(m + 8 + g) * PLD + kk + 2 * tg + 8];
            al[0] = *(const uint32_t*)&Pl[(m + g    ) * PLD + kk + 2 * tg    ];
            al[1] = *(const uint32_t*)&Pl[(m + 8 + g) * PLD + kk + 2 * tg    ];
            al[2] = *(const uint32_t*)&Pl[(m + g    ) * PLD + kk + 2 * tg + 8];
            al[3] = *(const uint32_t*)&Pl[(m + 8 + g) * PLD + kk + 2 * tg + 8];
#pragma unroll
            for (int nt = 0; nt < 4; nt++) {
                const int n = wn * 32 + nt * 8 + g;
                uint32_t bh[2], bl[2];
                bh[0] = *(const uint32_t*)&Vh[n * PLD + kk + 2 * tg    ];
                bh[1] = *(const uint32_t*)&Vh[n * PLD + kk + 2 * tg + 8];
                bl[0] = *(const uint32_t*)&Vl[n * PLD + kk + 2 * tg    ];
                bl[1] = *(const uint32_t*)&Vl[n * PLD + kk + 2 * tg + 8];
                mma_bf16(acc[nt], ah, bh);
                mma_bf16(acc[nt], ah, bl);
                mma_bf16(acc[nt], al, bh);
            }
        }
        __syncthreads();
    }

    // ---- epilogue: normalize by l, write to g_o ----
    const float i0 = 1.0f / sm_l[wm * 16 + g];
    const float i1 = 1.0f / sm_l[wm * 16 + 8 + g];
    float* obase = g_o + (size_t)(b * Tt) * Dd + h * HDd;
    const int r = q0 + wm * 16 + g;
#pragma unroll
    for (int nt = 0; nt < 4; nt++) {
        const int c = wn * 32 + nt * 8 + tg * 2;
        float2 v0 = make_float2(acc[nt][0] * i0, acc[nt][1] * i0);
        float2 v1 = make_float2(acc[nt][2] * i1, acc[nt][3] * i1);
        *(float2*)&obase[(size_t)r * Dd + c]       = v0;
        *(float2*)&obase[(size_t)(r + 8) * Dd + c] = v1;
    }
}

// ---------------- KNN memory attention + gate -> exact bf16 ---------------------
__global__ __launch_bounds__(512) void memcomb_kernel(
    const float* __restrict__ mem_bank, const int* __restrict__ knn_idx,
    const float* __restrict__ gate_bias)
{
    const int t = blockIdx.x, b = blockIdx.y;
    const int h = threadIdx.x >> 5;
    const int lane = threadIdx.x & 31;
    const int row = b * Tt + t;
    const int d0 = h * HDd + lane;
    const int d1 = d0 + 32;

    const float* qrow = g_q + (size_t)row * Dd;
    const float qa = qrow[d0], qb = qrow[d1];

    int idx[3];
#pragma unroll
    for (int kk = 0; kk < 3; kk++) idx[kk] = knn_idx[row * Kknn + kk];

    float dots[3];
#pragma unroll
    for (int kk = 0; kk < 3; kk++) {
        const float* mk = mem_bank + ((size_t)(b * Mm + idx[kk]) * 2) * Dd;
        float p = qa * mk[d0] + qb * mk[d1];
#pragma unroll
        for (int o = 16; o; o >>= 1) p += __shfl_xor_sync(0xffffffffu, p, o);
        dots[kk] = p * SCALE_F;
    }
    float m = fmaxf(dots[0], fmaxf(dots[1], dots[2]));
    float w[3];
    w[0] = __expf(dots[0] - m);
    w[1] = __expf(dots[1] - m);
    w[2] = __expf(dots[2] - m);
    float inv = 1.0f / (w[0] + w[1] + w[2]);
    w[0] *= inv; w[1] *= inv; w[2] *= inv;

    float oa = 0.f, ob = 0.f;
#pragma unroll
    for (int kk = 0; kk < 3; kk++) {
        const float* mv = mem_bank + ((size_t)(b * Mm + idx[kk]) * 2 + 1) * Dd;
        oa = fmaf(w[kk], mv[d0], oa);
        ob = fmaf(w[kk], mv[d1], ob);
    }

    const float gbv = gate_bias[h];
    const float* orow = g_o + (size_t)row * Dd;
    float ca = oa * gbv + orow[d0] * (1.0f - gbv);
    float cb = ob * gbv + orow[d1] * (1.0f - gbv);
    g_obf[(size_t)row * Dd + d0] = __float2bfloat16(ca);
    g_obf[(size_t)row * Dd + d1] = __float2bfloat16(cb);
}

// -------------------------------- launch ----------------------------------------
extern "C" void kernel_launch(void* const* d_in, const int* in_sizes, int n_in,
                              void* d_out, int out_size)
{
    const float* x    = (const float*)d_in[0];
    const float* Wq   = (const float*)d_in[1];
    const float* bq   = (const float*)d_in[2];
    const float* Wk   = (const float*)d_in[3];
    const float* bk   = (const float*)d_in[4];
    const float* Wv   = (const float*)d_in[5];
    const float* bv   = (const float*)d_in[6];
    const float* Wo   = (const float*)d_in[7];
    const float* bo   = (const float*)d_in[8];
    const float* gate = (const float*)d_in[9];
    const float* mem  = (const float*)d_in[10];
    const int*   knn  = (const int*)d_in[11];
    float* out = (float*)d_out;

    float *q, *k, *v, *o;
    cudaGetSymbolAddress((void**)&q, g_q);
    cudaGetSymbolAddress((void**)&k, g_k);
    cudaGetSymbolAddress((void**)&v, g_v);
    cudaGetSymbolAddress((void**)&o, g_o);
    __nv_bfloat16 *obf, *xh, *xl, *wvh, *wvl, *woh, *wol;
    cudaGetSymbolAddress((void**)&obf, g_obf);
    cudaGetSymbolAddress((void**)&xh,  g_xh);
    cudaGetSymbolAddress((void**)&xl,  g_xl);
    cudaGetSymbolAddress((void**)&wvh, g_wvh);
    cudaGetSymbolAddress((void**)&wvl, g_wvl);
    cudaGetSymbolAddress((void**)&woh, g_woh);
    cudaGetSymbolAddress((void**)&wol, g_wol);

    // 0) pre-split x, Wv, Wo into bf16 hi/lo planes
    split_kernel<<<(Nn * Dd / 4 + 255) / 256, 256>>>(x, xh, xl, Nn * Dd / 4);
    split_kernel<<<(Dd * Dd / 4 + 255) / 256, 256>>>(Wv, wvh, wvl, Dd * Dd / 4);
    split_kernel<<<(Dd * Dd / 4 + 255) / 256, 256>>>(Wo, woh, wol, Dd * Dd / 4);

    // 1) Q, K projections (3xTF32)
    {
        dim3 grid(Dd / 128, Nn / 128, 2);
        gemm_tf32_kernel<<<grid, 256>>>(x, Wq, bq, q, Wk, bk, k);
    }
    // 1b) V projection (bf16 3x)
    {
        dim3 grid(Dd / 128, Nn / 128, 1);
        gemm_bf16_kernel<1><<<grid, 256>>>(xh, xl, wvh, wvl, bv, v);
    }
    // 2) normalize q, k rows
    {
        dim3 grid(Nn, 2);
        normalize_kernel<<<grid, 256>>>();
    }
    // 3) causal flash attention
    {
        const int smem_bytes = 3 * 64 * ALD * (int)sizeof(float)
                             + 4 * 64 * PLD * (int)sizeof(uint16_t);
        cudaFuncSetAttribute(attn_kernel,
                             cudaFuncAttributeMaxDynamicSharedMemorySize, smem_bytes);
        dim3 grid(Tt / 64, Hh, Bb);
        attn_kernel<<<grid, 256, smem_bytes>>>();
    }
    // 4) KNN memory attention + gate -> exact bf16 combined
    {
        dim3 grid(Tt, Bb);
        memcomb_kernel<<<grid, 512>>>(mem, knn, gate);
    }
    // 5) output projection (bf16 2x: A exact in bf16) -> d_out
    {
        dim3 grid(Dd / 128, Nn / 128, 1);
        gemm_bf16_kernel<0><<<grid, 256>>>(obf, nullptr, woh, wol, bo, out);
    }
}